// round 1
// baseline (speedup 1.0000x reference)
#include <cuda_runtime.h>
#include <math.h>

#define BATCH 16
#define HW 65536
#define NPIX (BATCH*HW)

// ---- scratch (device globals; no allocation allowed) ----
__device__ float dS[NPIX];                 // sum-over-channels box-pooled field
__device__ float dMn[128];
__device__ float dMx[128];
__device__ float dHist[4096];              // 64 groups x 64 bins
__device__ float dTotal;
__device__ float dYq[BATCH*64*56*4];       // [b][p][oc][g]
__device__ float dMean[64];
__device__ float dInv[64];
__device__ float dZg[BATCH*64*56*16];      // [b][gh][gw][m]

// LBP neighbor offsets per output channel o (pos - center)
__device__ __forceinline__ int lbp_dy(int o){ const int d[8]={-1,1,-1,1,-1,1,0,0}; return d[o]; }
__device__ __forceinline__ int lbp_dx(int o){ const int d[8]={-1,1,0,0,1,-1,1,-1}; return d[o]; }

__device__ __forceinline__ float lrelu(float v){ return v >= 0.f ? v : 0.01f*v; }

// ---- K0: zero histogram ----
__global__ void k_zero(){
    int i = blockIdx.x*256 + threadIdx.x;
    if (i < 4096) dHist[i] = 0.f;
}

// ---- K1: S = box3x3(sum_c x)/9 with zero pad ----
__global__ void k_pool(const float* __restrict__ x){
    __shared__ float tile[10][34];
    int b  = blockIdx.z;
    int h0 = blockIdx.y*8, w0 = blockIdx.x*32;
    const float* xb = x + (size_t)b*3*HW;
    int tid = threadIdx.y*32 + threadIdx.x;
    for (int i = tid; i < 340; i += 256){
        int r = i/34, c = i - r*34;
        int h = h0-1+r, w = w0-1+c;
        float t = 0.f;
        if ((unsigned)h < 256u && (unsigned)w < 256u){
            int off = (h<<8) | w;
            t = xb[off] + xb[HW+off] + xb[2*HW+off];
        }
        tile[r][c] = t;
    }
    __syncthreads();
    int r = threadIdx.y, c = threadIdx.x;
    float s = tile[r  ][c] + tile[r  ][c+1] + tile[r  ][c+2]
            + tile[r+1][c] + tile[r+1][c+1] + tile[r+1][c+2]
            + tile[r+2][c] + tile[r+2][c+1] + tile[r+2][c+2];
    dS[b*HW + ((h0+r)<<8) + (w0+c)] = s / 9.0f;
}

// ---- K2: min/max per (b,o) of clamped LBP value ----
__global__ void k_minmax(const float* __restrict__ clo, const float* __restrict__ chi){
    int bo = blockIdx.x;                 // 0..127
    int b = bo >> 3, o = bo & 7;
    const float* Sb = dS + b*HW;
    float lo = clo[0], hi = chi[0];
    int dy = lbp_dy(o), dx = lbp_dx(o);
    float mn = 3.4e38f, mx = -3.4e38f;
    for (int p = threadIdx.x; p < HW; p += 256){
        int h = p>>8, w = p&255;
        float v = Sb[p];
        int hn = h+dy, wn = w+dx;
        float nb = ((unsigned)hn < 256u && (unsigned)wn < 256u) ? Sb[(hn<<8)+wn] : 0.f;
        v = fminf(fmaxf(v - nb, lo), hi);
        mn = fminf(mn, v); mx = fmaxf(mx, v);
    }
    __shared__ float smn[256], smx[256];
    smn[threadIdx.x] = mn; smx[threadIdx.x] = mx;
    __syncthreads();
    for (int s = 128; s > 0; s >>= 1){
        if (threadIdx.x < s){
            smn[threadIdx.x] = fminf(smn[threadIdx.x], smn[threadIdx.x+s]);
            smx[threadIdx.x] = fmaxf(smx[threadIdx.x], smx[threadIdx.x+s]);
        }
        __syncthreads();
    }
    if (threadIdx.x == 0){ dMn[bo] = smn[0]; dMx[bo] = smx[0]; }
}

// ---- K3: product histogram. grid (16 chunks, 64 groups) ----
__global__ void k_hist(const float* __restrict__ clo, const float* __restrict__ chi){
    int g64 = blockIdx.y;                // 0..63  (= b*4+g)
    int b = g64 >> 2, g = g64 & 3;
    __shared__ float sh[8][64];          // per-warp histogram
    __shared__ float lv0[8], hb0[8], lv1[8], hb1[8];
    int tid = threadIdx.x, warp = tid >> 5;
    for (int i = tid; i < 512; i += 256) ((float*)sh)[i] = 0.f;
    if (tid == 0){
        int bo0 = b*8 + 2*g, bo1 = bo0 + 1;
        float mn0 = dMn[bo0], mx0 = dMx[bo0];
        float mn1 = dMn[bo1], mx1 = dMx[bo1];
        float r0 = mx0 - mn0, r1 = mx1 - mn1;
        for (int q = 0; q < 8; q++){
            lv0[q] = __fadd_rn(mn0, __fmul_rn(r0, q*0.125f));
            lv1[q] = __fadd_rn(mn1, __fmul_rn(r1, q*0.125f));
        }
        for (int q = 0; q < 7; q++){ hb0[q] = lv0[q+1]; hb1[q] = lv1[q+1]; }
        hb0[7] = mx0; hb1[7] = mx1;
    }
    __syncthreads();
    int o0 = 2*g, o1 = 2*g + 1;
    int dy0 = lbp_dy(o0), dx0 = lbp_dx(o0);
    int dy1 = lbp_dy(o1), dx1 = lbp_dx(o1);
    const float* Sb = dS + b*HW;
    float lo = clo[0], hic = chi[0];
    int p0 = blockIdx.x * 4096;
    for (int p = p0 + tid; p < p0 + 4096; p += 256){
        int h = p>>8, w = p&255;
        float c = Sb[p];
        int hn = h+dy0, wn = w+dx0;
        float nb0 = ((unsigned)hn < 256u && (unsigned)wn < 256u) ? Sb[(hn<<8)+wn] : 0.f;
        hn = h+dy1; wn = w+dx1;
        float nb1 = ((unsigned)hn < 256u && (unsigned)wn < 256u) ? Sb[(hn<<8)+wn] : 0.f;
        float v0 = fminf(fmaxf(c - nb0, lo), hic);
        float v1 = fminf(fmaxf(c - nb1, lo), hic);
        unsigned m0 = 0, m1 = 0;
        #pragma unroll
        for (int q = 0; q < 8; q++){
            m0 |= (unsigned)(v0 >= lv0[q] && v0 <= hb0[q]) << q;
            m1 |= (unsigned)(v1 >= lv1[q] && v1 <= hb1[q]) << q;
        }
        float prod = v0 * v1;
        while (m0){
            int qi = __ffs(m0) - 1; m0 &= m0 - 1;
            unsigned t = m1;
            while (t){
                int qj = __ffs(t) - 1; t &= t - 1;
                atomicAdd(&sh[warp][qi*8 + qj], prod);
            }
        }
    }
    __syncthreads();
    for (int i = tid; i < 64; i += 256){
        float s = sh[0][i]+sh[1][i]+sh[2][i]+sh[3][i]+sh[4][i]+sh[5][i]+sh[6][i]+sh[7][i];
        atomicAdd(&dHist[g64*64 + i], s);
    }
}

// ---- K4a: global hist sum ----
__global__ void k_total(){
    __shared__ float sr[256];
    float s = 0.f;
    for (int i = threadIdx.x; i < 4096; i += 256) s += dHist[i];
    sr[threadIdx.x] = s;
    __syncthreads();
    for (int st = 128; st > 0; st >>= 1){
        if (threadIdx.x < st) sr[threadIdx.x] += sr[threadIdx.x+st];
        __syncthreads();
    }
    if (threadIdx.x == 0) dTotal = sr[0];
}

// ---- K4b: expand 1x1 conv on (i_idx, j_idx, hist) features ----
__global__ void k_yq(const float* __restrict__ we, const float* __restrict__ be){
    int idx = blockIdx.x*256 + threadIdx.x;
    if (idx >= BATCH*64*56*4) return;
    int g   = idx & 3;
    int rest = idx >> 2;
    int oc  = rest % 56;
    int rest2 = rest / 56;
    int p   = rest2 & 63;
    int b   = rest2 >> 6;
    float hn = dHist[(b*4+g)*64 + p] / dTotal;
    float v = we[oc*3+0]*(float)(p>>3) + we[oc*3+1]*(float)(p&7) + we[oc*3+2]*hn + be[oc];
    dYq[idx] = lrelu(v);
}

// ---- K4c: instance-norm stats via weighted sums on the 64x56 grid ----
__global__ void k_stats(){
    int bg = blockIdx.x;                 // 0..63
    int b = bg >> 2, g = bg & 3;
    float s = 0.f, sq = 0.f;
    for (int e = threadIdx.x; e < 3584; e += 256){
        int p = e / 56, oc = e - p*56;
        int cnt = (((oc+1)*256 + 55)/56) - ((oc*256 + 55)/56);   // #cols mapping to oc
        float wgt = (float)(cnt*4);
        float v = dYq[((b*64+p)*56+oc)*4 + g];
        s  += v*wgt;
        sq += v*v*wgt;
    }
    __shared__ float ss[256], ssq[256];
    ss[threadIdx.x] = s; ssq[threadIdx.x] = sq;
    __syncthreads();
    for (int st = 128; st > 0; st >>= 1){
        if (threadIdx.x < st){ ss[threadIdx.x] += ss[threadIdx.x+st]; ssq[threadIdx.x] += ssq[threadIdx.x+st]; }
        __syncthreads();
    }
    if (threadIdx.x == 0){
        float mean = ss[0] / 65536.f;
        float var  = ssq[0] / 65536.f - mean*mean;
        dMean[bg] = mean;
        dInv[bg]  = 1.f / sqrtf(fmaxf(var, 0.f) + 1e-5f);
    }
}

// ---- K4d: normalized 1x1 conv 4->16 on the grid ----
__global__ void k_zg(const float* __restrict__ wc, const float* __restrict__ bc){
    int idx = blockIdx.x*256 + threadIdx.x;
    if (idx >= BATCH*64*56*16) return;
    int m = idx & 15;
    int rest = idx >> 4;
    int oc = rest % 56;
    int rest2 = rest / 56;
    int p = rest2 & 63;
    int b = rest2 >> 6;
    float acc = bc[m];
    #pragma unroll
    for (int g = 0; g < 4; g++){
        float y = dYq[((b*64+p)*56+oc)*4 + g];
        acc += wc[m*4+g] * (y - dMean[b*4+g]) * dInv[b*4+g];
    }
    dZg[idx] = lrelu(acc);
}

// ---- K5: final 3x3 conv 16->1 on the upsampled (piecewise-constant) field ----
__global__ void k_final(const float* __restrict__ wf, const float* __restrict__ bf,
                        float* __restrict__ out){
    __shared__ float swf[144];
    int tid = threadIdx.x;
    if (tid < 144) swf[tid] = wf[tid];
    __syncthreads();
    int h = blockIdx.x, b = blockIdx.y, w = tid;
    float acc = 0.f;
    #pragma unroll
    for (int i = -1; i <= 1; i++){
        int hh = h + i;
        if ((unsigned)hh >= 256u) continue;
        int gh = hh >> 2;
        #pragma unroll
        for (int j = -1; j <= 1; j++){
            int ww = w + j;
            if ((unsigned)ww >= 256u) continue;
            int gw = (ww*56) >> 8;
            const float4* zp = (const float4*)&dZg[((b*64+gh)*56+gw)*16];
            int wb = (i+1)*3 + (j+1);
            #pragma unroll
            for (int m4 = 0; m4 < 4; m4++){
                float4 z = zp[m4];
                acc += swf[(m4*4+0)*9 + wb] * z.x;
                acc += swf[(m4*4+1)*9 + wb] * z.y;
                acc += swf[(m4*4+2)*9 + wb] * z.z;
                acc += swf[(m4*4+3)*9 + wb] * z.w;
            }
        }
    }
    acc += bf[0];
    out[(b<<16) | (h<<8) | w] = lrelu(acc);
}

extern "C" void kernel_launch(void* const* d_in, const int* in_sizes, int n_in,
                              void* d_out, int out_size){
    const float* x    = (const float*)d_in[0];
    const float* we   = (const float*)d_in[1];
    const float* be   = (const float*)d_in[2];
    const float* wc   = (const float*)d_in[3];
    const float* bc   = (const float*)d_in[4];
    const float* wfin = (const float*)d_in[5];
    const float* bfin = (const float*)d_in[6];
    const float* clo  = (const float*)d_in[7];
    const float* chi  = (const float*)d_in[8];
    float* out = (float*)d_out;

    k_zero  <<<16, 256>>>();
    k_pool  <<<dim3(8,32,16), dim3(32,8)>>>(x);
    k_minmax<<<128, 256>>>(clo, chi);
    k_hist  <<<dim3(16,64), 256>>>(clo, chi);
    k_total <<<1, 256>>>();
    k_yq    <<<(BATCH*64*56*4 + 255)/256, 256>>>(we, be);
    k_stats <<<64, 256>>>();
    k_zg    <<<(BATCH*64*56*16 + 255)/256, 256>>>(wc, bc);
    k_final <<<dim3(256,16), 256>>>(wfin, bfin, out);
}

// round 3
// speedup vs baseline: 1.2679x; 1.2679x over previous
#include <cuda_runtime.h>
#include <math.h>

#define BATCH 16
#define HW 65536

// ---- scratch (device globals) ----
__device__ float    dS[BATCH*HW];
__device__ unsigned dMnKey[128];
__device__ unsigned dMxKey[128];
__device__ float    dHist[4096];
__device__ float    dTotal;
__device__ float    dYq[BATCH*64*56*4];
__device__ float    dMean[64];
__device__ float    dInv[64];
__device__ float    dZg[BATCH*64*56*16];

__device__ __forceinline__ float lrelu(float v){ return v >= 0.f ? v : 0.01f*v; }

// monotone float<->uint ordering keys
__device__ __forceinline__ unsigned toKey(float f){
    unsigned u = __float_as_uint(f);
    return (u & 0x80000000u) ? ~u : (u | 0x80000000u);
}
__device__ __forceinline__ float fromKey(unsigned k){
    unsigned u = (k & 0x80000000u) ? (k & 0x7FFFFFFFu) : ~k;
    return __uint_as_float(u);
}

// ---- K0: init scratch ----
__global__ void k_init(){
    int t = threadIdx.x;
    for (int i = t; i < 4096; i += 256) dHist[i] = 0.f;
    if (t < 128){ dMnKey[t] = 0xFFFFFFFFu; dMxKey[t] = 0u; }
    if (t == 0) dTotal = 0.f;
}

// ---- K1: fused box-pool (sum over channels) + per-orientation clamped-LBP min/max ----
__global__ void __launch_bounds__(256) k_pool_minmax(const float* __restrict__ x,
                                                     const float* __restrict__ clo,
                                                     const float* __restrict__ chi){
    __shared__ float xs[20][36];   // sum-of-3-channels, halo 2
    __shared__ float St[18][34];   // pooled S, halo 1
    __shared__ float red[8][16];
    int b  = blockIdx.z;
    int h0 = blockIdx.y*16, w0 = blockIdx.x*32;
    int tx = threadIdx.x, ty = threadIdx.y;
    int tid = ty*32 + tx;
    const float* xb = x + (size_t)b*3*HW;

    for (int i = tid; i < 720; i += 256){
        int r = i/36, c = i - r*36;
        int h = h0-2+r, w = w0-2+c;
        float v = 0.f;
        if ((unsigned)h < 256u && (unsigned)w < 256u){
            int off = (h<<8) | w;
            v = xb[off] + xb[HW+off] + xb[2*HW+off];
        }
        xs[r][c] = v;
    }
    __syncthreads();

    for (int i = tid; i < 612; i += 256){
        int r = i/34, c = i - r*34;
        int h = h0-1+r, w = w0-1+c;
        float s = 0.f;
        if ((unsigned)h < 256u && (unsigned)w < 256u){
            s = (xs[r  ][c] + xs[r  ][c+1] + xs[r  ][c+2]
               + xs[r+1][c] + xs[r+1][c+1] + xs[r+1][c+2]
               + xs[r+2][c] + xs[r+2][c+1] + xs[r+2][c+2]) / 9.0f;
            if (r >= 1 && r < 17 && c >= 1 && c < 33)
                dS[b*HW + (h<<8) + w] = s;
        }
        St[r][c] = s;
    }
    __syncthreads();

    const int DY[8] = {-1,1,-1,1,-1,1,0,0};
    const int DX[8] = {-1,1,0,0,1,-1,1,-1};
    float lo = clo[0], hi = chi[0];
    float mn[8], mx[8];
    #pragma unroll
    for (int o = 0; o < 8; o++){ mn[o] = 3.4e38f; mx[o] = -3.4e38f; }

    #pragma unroll
    for (int ph = 0; ph < 2; ph++){
        int r = ty + ph*8 + 1, c = tx + 1;
        float ctr = St[r][c];
        #pragma unroll
        for (int o = 0; o < 8; o++){
            float v = fminf(fmaxf(ctr - St[r+DY[o]][c+DX[o]], lo), hi);
            mn[o] = fminf(mn[o], v);
            mx[o] = fmaxf(mx[o], v);
        }
    }
    // warp reduce
    #pragma unroll
    for (int o = 0; o < 8; o++){
        #pragma unroll
        for (int off = 16; off; off >>= 1){
            mn[o] = fminf(mn[o], __shfl_xor_sync(0xffffffffu, mn[o], off));
            mx[o] = fmaxf(mx[o], __shfl_xor_sync(0xffffffffu, mx[o], off));
        }
    }
    int warp = tid >> 5, lane = tid & 31;
    if (lane == 0){
        #pragma unroll
        for (int o = 0; o < 8; o++){ red[warp][o] = mn[o]; red[warp][8+o] = mx[o]; }
    }
    __syncthreads();
    if (tid < 16){
        if (tid < 8){
            float v = red[0][tid];
            #pragma unroll
            for (int w2 = 1; w2 < 8; w2++) v = fminf(v, red[w2][tid]);
            atomicMin(&dMnKey[b*8 + tid], toKey(v));
        } else {
            float v = red[0][tid];
            #pragma unroll
            for (int w2 = 1; w2 < 8; w2++) v = fmaxf(v, red[w2][tid]);
            atomicMax(&dMxKey[b*8 + tid - 8], toKey(v));
        }
    }
}

// ---- K2: fused product histogram (all 4 groups per pass) + global total ----
__global__ void __launch_bounds__(256) k_hist(const float* __restrict__ clo,
                                              const float* __restrict__ chi){
    __shared__ float St[18][34];
    __shared__ float sh[8][256];     // per-warp: 4 groups x 64 bins
    __shared__ float lv[8][8];
    __shared__ float smn[8], sscale[8];
    __shared__ float redt[8];
    int b  = blockIdx.z;
    int h0 = blockIdx.y*16, w0 = blockIdx.x*32;
    int tid = threadIdx.x;
    int warp = tid >> 5, lane = tid & 31;
    const float* Sb = dS + b*HW;

    for (int i = tid; i < 612; i += 256){
        int r = i/34, c = i - r*34;
        int h = h0-1+r, w = w0-1+c;
        St[r][c] = ((unsigned)h < 256u && (unsigned)w < 256u) ? Sb[(h<<8)+w] : 0.f;
    }
    for (int i = tid; i < 2048; i += 256) ((float*)sh)[i] = 0.f;
    if (tid < 64){
        int o = tid >> 3, q = tid & 7;
        float mnv = fromKey(dMnKey[b*8+o]);
        float mxv = fromKey(dMxKey[b*8+o]);
        float r = mxv - mnv;
        lv[o][q] = __fadd_rn(mnv, __fmul_rn(r, q*0.125f));
        if (q == 0){ smn[o] = mnv; sscale[o] = (r > 0.f) ? 8.0f/r : 0.f; }
    }
    __syncthreads();

    const int DY[8] = {-1,1,-1,1,-1,1,0,0};
    const int DX[8] = {-1,1,0,0,1,-1,1,-1};
    float lo = clo[0], hi = chi[0];
    int tx = tid & 31, ty = tid >> 5;

    #pragma unroll
    for (int ph = 0; ph < 2; ph++){
        int r = ty + ph*8 + 1, c = tx + 1;
        float ctr = St[r][c];
        float vv[8]; int qq[8]; unsigned tie = 0;
        #pragma unroll
        for (int o = 0; o < 8; o++){
            float v = fminf(fmaxf(ctr - St[r+DY[o]][c+DX[o]], lo), hi);
            float f = (v - smn[o]) * sscale[o];
            int q = (int)f; q = q < 0 ? 0 : (q > 7 ? 7 : q);
            if (q < 7 && v >= lv[o][q+1]) q++;
            if (q < 7 && v >= lv[o][q+1]) q++;
            if (q > 0 && v <  lv[o][q])   q--;
            if (q > 0 && v <  lv[o][q])   q--;
            vv[o] = v; qq[o] = q;
            if (q > 0 && v == lv[o][q]) tie |= 1u << o;
        }
        #pragma unroll
        for (int g = 0; g < 4; g++){
            float prod = vv[2*g] * vv[2*g+1];
            int qi = qq[2*g], qj = qq[2*g+1];
            atomicAdd(&sh[warp][g*64 + qi*8 + qj], prod);
            if (tie & (3u << (2*g))){               // vanishingly rare (exact boundary tie)
                if (tie & (1u << (2*g)))   atomicAdd(&sh[warp][g*64 + (qi-1)*8 + qj], prod);
                if (tie & (1u << (2*g+1))) atomicAdd(&sh[warp][g*64 + qi*8 + (qj-1)], prod);
                if (((tie >> (2*g)) & 3u) == 3u)
                                           atomicAdd(&sh[warp][g*64 + (qi-1)*8 + (qj-1)], prod);
            }
        }
    }
    __syncthreads();

    float s;
    {
        int g = tid >> 6, bin = tid & 63;
        s = sh[0][g*64+bin] + sh[1][g*64+bin] + sh[2][g*64+bin] + sh[3][g*64+bin]
          + sh[4][g*64+bin] + sh[5][g*64+bin] + sh[6][g*64+bin] + sh[7][g*64+bin];
        atomicAdd(&dHist[(b*4+g)*64 + bin], s);
    }
    #pragma unroll
    for (int off = 16; off; off >>= 1) s += __shfl_xor_sync(0xffffffffu, s, off);
    if (lane == 0) redt[warp] = s;
    __syncthreads();
    if (tid == 0){
        float t = 0.f;
        #pragma unroll
        for (int w2 = 0; w2 < 8; w2++) t += redt[w2];
        atomicAdd(&dTotal, t);
    }
}

// ---- K3: expand 1x1 conv on (i_idx, j_idx, hist) features ----
__global__ void k_yq(const float* __restrict__ we, const float* __restrict__ be){
    int idx = blockIdx.x*256 + threadIdx.x;   // 229376 total
    int g    = idx & 3;
    int rest = idx >> 2;
    int oc   = rest % 56;
    int rest2 = rest / 56;
    int p    = rest2 & 63;
    int b    = rest2 >> 6;
    float hn = dHist[(b*4+g)*64 + p] / dTotal;
    float v = we[oc*3+0]*(float)(p>>3) + we[oc*3+1]*(float)(p&7) + we[oc*3+2]*hn + be[oc];
    dYq[idx] = lrelu(v);
}

// ---- K4: instance-norm stats via weighted sums on 64x56 grid ----
__global__ void k_stats(){
    int bg = blockIdx.x;                 // 0..63
    float s = 0.f, sq = 0.f;
    int g = bg & 3, b = bg >> 2;
    for (int e = threadIdx.x; e < 3584; e += 256){
        int p = e / 56, oc = e - p*56;
        int cnt = (((oc+1)*256 + 55)/56) - ((oc*256 + 55)/56);
        float wgt = (float)(cnt*4);
        float v = dYq[((b*64+p)*56+oc)*4 + g];
        s  += v*wgt;
        sq += v*v*wgt;
    }
    __shared__ float ss[256], ssq[256];
    ss[threadIdx.x] = s; ssq[threadIdx.x] = sq;
    __syncthreads();
    for (int st = 128; st > 0; st >>= 1){
        if (threadIdx.x < st){ ss[threadIdx.x] += ss[threadIdx.x+st]; ssq[threadIdx.x] += ssq[threadIdx.x+st]; }
        __syncthreads();
    }
    if (threadIdx.x == 0){
        float mean = ss[0] / 65536.f;
        float var  = ssq[0] / 65536.f - mean*mean;
        dMean[bg] = mean;
        dInv[bg]  = 1.f / sqrtf(fmaxf(var, 0.f) + 1e-5f);
    }
}

// ---- K5: normalized 1x1 conv 4->16 on the grid ----
__global__ void k_zg(const float* __restrict__ wc, const float* __restrict__ bc){
    int idx = blockIdx.x*256 + threadIdx.x;  // 917504 total
    int m = idx & 15;
    int rest = idx >> 4;
    int oc = rest % 56;
    int rest2 = rest / 56;
    int p = rest2 & 63;
    int b = rest2 >> 6;
    float acc = bc[m];
    #pragma unroll
    for (int g = 0; g < 4; g++){
        float y = dYq[((b*64+p)*56+oc)*4 + g];
        acc += wc[m*4+g] * (y - dMean[b*4+g]) * dInv[b*4+g];
    }
    dZg[idx] = lrelu(acc);
}

// ---- K6: final 3x3 conv 16->1 on upsampled piecewise-constant field (smem staged) ----
__global__ void __launch_bounds__(256) k_final(const float* __restrict__ wf,
                                               const float* __restrict__ bf,
                                               float* __restrict__ out){
    __shared__ float swf[144];
    __shared__ float buf[2][896];   // two zgrid rows: 56 cells x 16 ch
    int h = blockIdx.x, b = blockIdx.y;
    int tid = threadIdx.x;
    if (tid < 144) swf[tid] = wf[tid];
    int g0 = (h >= 1)   ? ((h-1) >> 2) : 0;
    int g1 = (h <= 254) ? ((h+1) >> 2) : 63;
    const float* z0 = &dZg[((size_t)(b*64 + g0))*896];
    const float* z1 = &dZg[((size_t)(b*64 + g1))*896];
    for (int i = tid; i < 896; i += 256){ buf[0][i] = z0[i]; buf[1][i] = z1[i]; }
    __syncthreads();

    int w = tid;
    float acc = bf[0];
    #pragma unroll
    for (int i = -1; i <= 1; i++){
        int hh = h + i;
        if ((unsigned)hh >= 256u) continue;
        int sel = ((hh >> 2) == g0) ? 0 : 1;
        #pragma unroll
        for (int j = -1; j <= 1; j++){
            int ww = w + j;
            if ((unsigned)ww >= 256u) continue;
            int gw = (ww*56) >> 8;
            const float4* zp = (const float4*)&buf[sel][gw*16];
            int wb = (i+1)*3 + (j+1);
            #pragma unroll
            for (int m4 = 0; m4 < 4; m4++){
                float4 z = zp[m4];
                acc += swf[(m4*4+0)*9 + wb] * z.x;
                acc += swf[(m4*4+1)*9 + wb] * z.y;
                acc += swf[(m4*4+2)*9 + wb] * z.z;
                acc += swf[(m4*4+3)*9 + wb] * z.w;
            }
        }
    }
    out[(b<<16) | (h<<8) | w] = lrelu(acc);
}

extern "C" void kernel_launch(void* const* d_in, const int* in_sizes, int n_in,
                              void* d_out, int out_size){
    const float* x    = (const float*)d_in[0];
    const float* we   = (const float*)d_in[1];
    const float* be   = (const float*)d_in[2];
    const float* wc   = (const float*)d_in[3];
    const float* bc   = (const float*)d_in[4];
    const float* wfin = (const float*)d_in[5];
    const float* bfin = (const float*)d_in[6];
    const float* clo  = (const float*)d_in[7];
    const float* chi  = (const float*)d_in[8];
    float* out = (float*)d_out;

    k_init       <<<1, 256>>>();
    k_pool_minmax<<<dim3(8,16,16), dim3(32,8)>>>(x, clo, chi);
    k_hist       <<<dim3(8,16,16), 256>>>(clo, chi);
    k_yq         <<<(BATCH*64*56*4 + 255)/256, 256>>>(we, be);   // 896 blocks
    k_stats      <<<64, 256>>>();
    k_zg         <<<(BATCH*64*56*16 + 255)/256, 256>>>(wc, bc);  // 3584 blocks
    k_final      <<<dim3(256,16), 256>>>(wfin, bfin, out);
}